// round 17
// baseline (speedup 1.0000x reference)
#include <cuda_runtime.h>
#include <cuda_fp16.h>
#include <math.h>
#include <stdint.h>

// ---------------- problem constants ----------------
#define BB 4
#define TT 1024
#define EE 768
#define HH 8
#define HS 96
#define LL 8
#define VV 32000
#define FF 3072            // 4*E
#define MM (BB*TT)         // 4096 rows
#define E2 (2*EE)          // 1536
#define E3 (3*EE)          // 2304 (QKV output width q|k|v)

typedef __half fp16;

// ---------------- scratch (device globals; no allocation allowed) ----------------
__device__ __align__(256) float g_x   [(size_t)MM*EE];
__device__ __align__(256) fp16  g_xn2 [(size_t)MM*E2];         // ln out (1-term pitch EE used)
__device__ __align__(256) fp16  g_qkv [(size_t)MM*E3];         // 1-term qkv
__device__ __align__(256) fp16  g_att2[(size_t)MM*E2];         // 2-term attention out
__device__ __align__(256) fp16  g_h42 [(size_t)MM*FF];         // 1-term h4

// weights: wqkv single [EE][E3]; wo dup [2EE][EE]; w1 single [EE][FF]; w2 single [FF][EE]; tok [EE][VV]
__device__ __align__(256) fp16  g_wqkv2[(size_t)LL*EE*E3];
__device__ __align__(256) fp16  g_wo2  [(size_t)LL*E2*EE];
__device__ __align__(256) fp16  g_w12  [(size_t)LL*EE*FF];
__device__ __align__(256) fp16  g_w22  [(size_t)LL*FF*EE];
__device__ __align__(256) fp16  g_tok2 [(size_t)EE*VV];

__device__ __align__(256) float g_logits_scratch[(size_t)MM*VV];

// ---------------- helpers ----------------
__device__ __forceinline__ void split2h(float v, fp16& hi, fp16& lo) {
    hi = __float2half(v);
    lo = __float2half(v - __half2float(hi));
}
__device__ __forceinline__ uint32_t pack2h(fp16 a, fp16 b) {
    uint16_t x = *(uint16_t*)&a, y = *(uint16_t*)&b;
    return (uint32_t)x | ((uint32_t)y << 16);
}
__device__ __forceinline__ void cp16(void* dst_smem, const void* src_gmem) {
    uint32_t s = (uint32_t)__cvta_generic_to_shared(dst_smem);
    asm volatile("cp.async.cg.shared.global [%0], [%1], 16;\n" :: "r"(s), "l"(src_gmem));
}
__device__ __forceinline__ void cp_commit() { asm volatile("cp.async.commit_group;\n" ::: "memory"); }
__device__ __forceinline__ void cp_wait1()  { asm volatile("cp.async.wait_group 1;\n" ::: "memory"); }

__device__ __forceinline__ void ldmA4(uint32_t* a, const void* p) {
    uint32_t s = (uint32_t)__cvta_generic_to_shared(p);
    asm volatile("ldmatrix.sync.aligned.m8n8.x4.shared.b16 {%0,%1,%2,%3}, [%4];"
                 : "=r"(a[0]), "=r"(a[1]), "=r"(a[2]), "=r"(a[3]) : "r"(s));
}
__device__ __forceinline__ void ldmB4t(uint32_t* b, const void* p) {
    uint32_t s = (uint32_t)__cvta_generic_to_shared(p);
    asm volatile("ldmatrix.sync.aligned.m8n8.x4.trans.shared.b16 {%0,%1,%2,%3}, [%4];"
                 : "=r"(b[0]), "=r"(b[1]), "=r"(b[2]), "=r"(b[3]) : "r"(s));
}
__device__ __forceinline__ void mma16816h(float* c, const uint32_t* a, const uint32_t* b) {
    asm volatile(
        "mma.sync.aligned.m16n8k16.row.col.f32.f16.f16.f32 "
        "{%0,%1,%2,%3},{%4,%5,%6,%7},{%8,%9},{%0,%1,%2,%3};"
        : "+f"(c[0]), "+f"(c[1]), "+f"(c[2]), "+f"(c[3])
        : "r"(a[0]), "r"(a[1]), "r"(a[2]), "r"(a[3]), "r"(b[0]), "r"(b[1]));
}

// ---------------- batched weight conversion (vectorized x4) -------------
// seg 3 (Wo): dup [2K][N]. all others: single [K][N].
__global__ void convert_all_kernel(const float* __restrict__ Wq, const float* __restrict__ Wk,
                                   const float* __restrict__ Wv, const float* __restrict__ Wo,
                                   const float* __restrict__ W1, const float* __restrict__ W2)
{
    const int l = blockIdx.y / 6, seg = blockIdx.y % 6;
    const float* W; fp16* out; int K, N, pitch, colOff; bool dup;
    switch (seg) {
        case 0: W = Wq + (size_t)l*EE*EE; out = g_wqkv2 + (size_t)l*EE*E3; K=EE; N=EE; pitch=E3; colOff=0;    dup=false; break;
        case 1: W = Wk + (size_t)l*EE*EE; out = g_wqkv2 + (size_t)l*EE*E3; K=EE; N=EE; pitch=E3; colOff=EE;   dup=false; break;
        case 2: W = Wv + (size_t)l*EE*EE; out = g_wqkv2 + (size_t)l*EE*E3; K=EE; N=EE; pitch=E3; colOff=2*EE; dup=false; break;
        case 3: W = Wo + (size_t)l*EE*EE; out = g_wo2   + (size_t)l*E2*EE; K=EE; N=EE; pitch=EE; colOff=0;    dup=true;  break;
        case 4: W = W1 + (size_t)l*EE*FF; out = g_w12   + (size_t)l*EE*FF; K=EE; N=FF; pitch=FF; colOff=0;    dup=false; break;
        default:W = W2 + (size_t)l*FF*EE; out = g_w22   + (size_t)l*FF*EE; K=FF; N=EE; pitch=EE; colOff=0;    dup=false; break;
    }
    int base = (blockIdx.x * 256 + threadIdx.x) * 4;
    if (base >= K * N) return;
    int k = base / N, n = base % N;
    float4 f = *(const float4*)&W[base];
    uint2 h;
    h.x = pack2h(__float2half(f.x), __float2half(f.y));
    h.y = pack2h(__float2half(f.z), __float2half(f.w));
    *(uint2*)&out[(size_t)k * pitch + colOff + n] = h;
    if (dup)
        *(uint2*)&out[(size_t)(K + k) * pitch + colOff + n] = h;
}

// Error contract: Wo keeps exact 2-term A (attention-out path). QKV, W1, W2, lm-head are
// 1-term; measured quadrature contributions ~1.7-2.8e-4 each, non-compounding.

// ---------------- tok transpose: out[EE, V] from tok[V, E] (1-term B) -------------
__global__ void convert_tok_kernel(const float* __restrict__ tok, fp16* __restrict__ out)
{
    __shared__ float t[32][33];
    int k0 = blockIdx.x * 32, n0 = blockIdx.y * 32;
    int tx = threadIdx.x, ty = threadIdx.y;
    t[ty][tx] = tok[(size_t)(n0 + ty) * EE + k0 + tx];
    __syncthreads();
    fp16 hi = __float2half(t[tx][ty]);
    size_t k = k0 + ty, n = n0 + tx;
    out[k * VV + n] = hi;
}

// ---------------- embedding ----------------
__global__ void embed_kernel(const int* __restrict__ idx,
                             const float* __restrict__ tok,
                             const float* __restrict__ pos,
                             float* __restrict__ x)
{
    size_t i = (size_t)blockIdx.x * blockDim.x + threadIdx.x;
    if (i >= (size_t)MM * EE) return;
    int e  = (int)(i % EE);
    int bt = (int)(i / EE);
    int t  = bt % TT;
    x[i] = tok[(size_t)idx[bt] * EE + e] + pos[(size_t)t * EE + e];
}

// ---------------- layernorm, warp-per-row -> single fp16, pitch EE ----------------
__global__ void ln_split_kernel(const float* __restrict__ x,
                                const float* __restrict__ g,
                                const float* __restrict__ b,
                                fp16* __restrict__ out)
{
    const int warp = threadIdx.x >> 5, lane = threadIdx.x & 31;
    const int row = blockIdx.x * 8 + warp;
    const float* xr = x + (size_t)row * EE;

    float4 v[6];
    float s = 0.f, s2 = 0.f;
#pragma unroll
    for (int j = 0; j < 6; j++) {
        v[j] = *(const float4*)&xr[(j * 32 + lane) * 4];
        s  += v[j].x + v[j].y + v[j].z + v[j].w;
        s2 += v[j].x * v[j].x + v[j].y * v[j].y + v[j].z * v[j].z + v[j].w * v[j].w;
    }
#pragma unroll
    for (int o = 16; o > 0; o >>= 1) {
        s  += __shfl_xor_sync(0xffffffffu, s,  o);
        s2 += __shfl_xor_sync(0xffffffffu, s2, o);
    }
    const float mean = s * (1.f / EE);
    const float var  = s2 * (1.f / EE) - mean * mean;
    const float inv  = rsqrtf(var + 1e-5f);

    fp16* orow = out + (size_t)row * EE;
#pragma unroll
    for (int j = 0; j < 6; j++) {
        const int e0 = (j * 32 + lane) * 4;
        float4 gg = *(const float4*)&g[e0];
        float4 bb = *(const float4*)&b[e0];
        float f0 = (v[j].x - mean) * inv * gg.x + bb.x;
        float f1 = (v[j].y - mean) * inv * gg.y + bb.y;
        float f2 = (v[j].z - mean) * inv * gg.z + bb.z;
        float f3 = (v[j].w - mean) * inv * gg.w + bb.w;
        uint2 hv;
        hv.x = pack2h(__float2half(f0), __float2half(f1));
        hv.y = pack2h(__float2half(f2), __float2half(f3));
        *(uint2*)&orow[e0] = hv;
    }
}

// ---------------- tensor-core GEMM: C[M,N] = A[M,K2] @ B[K2,N] (fp16, fp32 acc) --------
// OUTMODE: 0 = fp32 (+res), 2 = single fp16 pitch N.
template<int OUTMODE, bool GELU>
__global__ void __launch_bounds__(256, 2)
mma_gemm(const fp16* __restrict__ A, const fp16* __restrict__ B,
         const float* __restrict__ bias, const float* __restrict__ res,
         void* __restrict__ Cv, int M, int N, int K2, int lda)
{
    extern __shared__ char dynsm[];
    fp16* As = (fp16*)dynsm;             // [2][128*72]
    fp16* Bs = (fp16*)dynsm + 18432;     // [2][64*144]

    const int tid  = threadIdx.x;
    const int lane = tid & 31;
    const int warp = tid >> 5;
    const int wm   = warp & 1;
    const int wn   = warp >> 1;

    const int nRowT = M >> 7;
    const int nColT = N >> 7;
    const int nTiles = nRowT * nColT;
    const int ntk = K2 >> 6;

    for (int tile = blockIdx.x; tile < nTiles; tile += gridDim.x) {
        const int col0 = (tile / nRowT) * 128;
        const int row0 = (tile % nRowT) * 128;

        float acc[4][4][4];
#pragma unroll
        for (int i = 0; i < 4; i++)
#pragma unroll
            for (int j = 0; j < 4; j++)
#pragma unroll
                for (int r = 0; r < 4; r++) acc[i][j][r] = 0.f;

        auto load_tile = [&](int s, int k0) {
#pragma unroll
            for (int i = 0; i < 4; i++) {
                int idx = tid + i * 256;
                int r = idx >> 3, c = (idx & 7) * 8;
                cp16(&As[s * 9216 + r * 72 + c], &A[(size_t)(row0 + r) * lda + k0 + c]);
            }
#pragma unroll
            for (int i = 0; i < 4; i++) {
                int idx = tid + i * 256;
                int r = idx >> 4, c = (idx & 15) * 8;
                cp16(&Bs[s * 9216 + r * 144 + c], &B[(size_t)(k0 + r) * N + col0 + c]);
            }
        };

        __syncthreads();
        load_tile(0, 0);
        cp_commit();

        for (int t = 0; t < ntk; t++) {
            if (t + 1 < ntk) load_tile((t + 1) & 1, (t + 1) * 64);
            cp_commit();
            cp_wait1();
            __syncthreads();
            const int s = t & 1;

#pragma unroll
            for (int kk = 0; kk < 64; kk += 16) {
                uint32_t a[4][4], b[2][4];
#pragma unroll
                for (int mi = 0; mi < 4; mi++)
                    ldmA4(a[mi], &As[s * 9216 + (wm * 64 + mi * 16 + (lane & 15)) * 72 + kk + (lane >> 4) * 8]);
#pragma unroll
                for (int nj = 0; nj < 2; nj++)
                    ldmB4t(b[nj], &Bs[s * 9216 + (kk + (lane & 15)) * 144 + wn * 32 + nj * 16 + (lane >> 4) * 8]);
#pragma unroll
                for (int mi = 0; mi < 4; mi++) {
                    mma16816h(acc[mi][0], a[mi], b[0]);
                    mma16816h(acc[mi][1], a[mi], b[0] + 2);
                    mma16816h(acc[mi][2], a[mi], b[1]);
                    mma16816h(acc[mi][3], a[mi], b[1] + 2);
                }
            }
            __syncthreads();
        }

        // ---- epilogue ----
        const int gid = lane >> 2, tig = lane & 3;
#pragma unroll
        for (int mi = 0; mi < 4; mi++) {
#pragma unroll
            for (int ni = 0; ni < 4; ni++) {
                int gr = row0 + wm * 64 + mi * 16 + gid;
                int gc = col0 + wn * 32 + ni * 8 + tig * 2;
#pragma unroll
                for (int half = 0; half < 2; half++) {
                    int r = gr + half * 8;
#pragma unroll
                    for (int cc = 0; cc < 2; cc++) {
                        float c = acc[mi][ni][half * 2 + cc];
                        int col = gc + cc;
                        if (bias) c += bias[col];
                        if (GELU) c = 0.5f * c * (1.f + erff(c * 0.70710678118654752f));
                        if (OUTMODE == 2) {
                            fp16* C = (fp16*)Cv;
                            C[(size_t)r * N + col] = __float2half(c);
                        } else {
                            float* C = (float*)Cv;
                            if (res) c += res[(size_t)r * N + col];
                            C[(size_t)r * N + col] = c;
                        }
                    }
                }
            }
        }
    }
}

// ---------------- fp16 flash attention (1-term q/k/v), 2 CTAs/SM ----------------
// Smem: Qs[128][104] @0 (26624), Ks[96][72] @26624 (13824),
//       Vs[64][104] @40448 (13312), Ps[128][72] @53760 (18432). Total 72192.
__global__ void __launch_bounds__(256, 2)
attn_mma_kernel(const fp16* __restrict__ qkv, fp16* __restrict__ att2)
{
    extern __shared__ char dynsm[];
    fp16* Qs = (fp16*)dynsm;
    fp16* Ks = (fp16*)(dynsm + 26624);
    fp16* Vs = (fp16*)(dynsm + 40448);
    fp16* Ps = (fp16*)(dynsm + 53760);

    const int qb0  = blockIdx.x * 128;
    const int h    = blockIdx.y;
    const int b    = blockIdx.z;
    const int tid  = threadIdx.x;
    const int lane = tid & 31;
    const int w    = tid >> 5;
    const int gid  = lane >> 2, tig = lane & 3;

    const size_t NQ = E3;
    const size_t rowbase = (size_t)(b * TT) * NQ;
    const int qoff = h * HS, koff = EE + h * HS, voff = 2 * EE + h * HS;

    for (int i = tid; i < 128 * 12; i += 256) {
        int r = i / 12, e0 = (i % 12) * 8;
        *(uint4*)&Qs[r * 104 + e0] = *(const uint4*)&qkv[rowbase + (size_t)(qb0 + r) * NQ + qoff + e0];
    }

    float o[12][4];
#pragma unroll
    for (int i = 0; i < 12; i++)
#pragma unroll
        for (int j = 0; j < 4; j++) o[i][j] = 0.f;
    float mrow0 = -1e30f, mrow1 = -1e30f, lrow0 = 0.f, lrow1 = 0.f;

    const float scale = 0.10206207261596577f;
    const int nchunks = qb0 / 64 + 2;

    for (int ch = 0; ch < nchunks; ch++) {
        const int c0 = ch * 64;
        __syncthreads();
        for (int i = tid; i < 64 * 12; i += 256) {
            int key = i / 12, e0 = (i % 12) * 8;
            const size_t g = rowbase + (size_t)(c0 + key) * NQ;
            uint4 khiv = *(const uint4*)&qkv[g + koff + e0];
            const fp16* kh = (const fp16*)&khiv;
#pragma unroll
            for (int j = 0; j < 8; j++)
                Ks[(e0 + j) * 72 + key] = kh[j];
            *(uint4*)&Vs[key * 104 + e0] = *(const uint4*)&qkv[g + voff + e0];
        }
        __syncthreads();

        float sacc[8][4];
#pragma unroll
        for (int i = 0; i < 8; i++)
#pragma unroll
            for (int j = 0; j < 4; j++) sacc[i][j] = 0.f;

#pragma unroll
        for (int kk = 0; kk < 96; kk += 16) {
            uint32_t a[4];
            ldmA4(a, &Qs[(w * 16 + (lane & 15)) * 104 + kk + (lane >> 4) * 8]);
#pragma unroll
            for (int nt = 0; nt < 8; nt += 2) {
                uint32_t bb[4];
                ldmB4t(bb, &Ks[(kk + (lane & 15)) * 72 + nt * 8 + (lane >> 4) * 8]);
                mma16816h(sacc[nt],     a, bb);
                mma16816h(sacc[nt + 1], a, bb + 2);
            }
        }

        const int rg0 = qb0 + w * 16 + gid;
        const bool need_mask = (c0 + 64 > qb0);
        float cm0 = -1e30f, cm1 = -1e30f;
#pragma unroll
        for (int nt = 0; nt < 8; nt++) {
#pragma unroll
            for (int e = 0; e < 4; e++) {
                float s = sacc[nt][e] * scale;
                if (need_mask) {
                    int col = c0 + nt * 8 + tig * 2 + (e & 1);
                    int row = rg0 + (e >> 1) * 8;
                    if (col > row) s = -1e30f;
                }
                sacc[nt][e] = s;
                if (e < 2) cm0 = fmaxf(cm0, s); else cm1 = fmaxf(cm1, s);
            }
        }
        cm0 = fmaxf(cm0, __shfl_xor_sync(0xffffffffu, cm0, 1));
        cm0 = fmaxf(cm0, __shfl_xor_sync(0xffffffffu, cm0, 2));
        cm1 = fmaxf(cm1, __shfl_xor_sync(0xffffffffu, cm1, 1));
        cm1 = fmaxf(cm1, __shfl_xor_sync(0xffffffffu, cm1, 2));

        const float mn0 = fmaxf(mrow0, cm0), mn1 = fmaxf(mrow1, cm1);
        const float al0 = __expf(mrow0 - mn0), al1 = __expf(mrow1 - mn1);
        float cs0 = 0.f, cs1 = 0.f;
#pragma unroll
        for (int nt = 0; nt < 8; nt++) {
            float p0 = __expf(sacc[nt][0] - mn0), p1 = __expf(sacc[nt][1] - mn0);
            float p2 = __expf(sacc[nt][2] - mn1), p3 = __expf(sacc[nt][3] - mn1);
            cs0 += p0 + p1; cs1 += p2 + p3;
            int colb = nt * 8 + tig * 2;
            *(uint32_t*)&Ps[(w * 16 + gid) * 72 + colb]     = pack2h(__float2half(p0), __float2half(p1));
            *(uint32_t*)&Ps[(w * 16 + gid + 8) * 72 + colb] = pack2h(__float2half(p2), __float2half(p3));
        }
        cs0 += __shfl_xor_sync(0xffffffffu, cs0, 1);
        cs0 += __shfl_xor_sync(0xffffffffu, cs0, 2);
        cs1 += __shfl_xor_sync(0xffffffffu, cs1, 1);
        cs1 += __shfl_xor_sync(0xffffffffu, cs1, 2);

        lrow0 = lrow0 * al0 + cs0; lrow1 = lrow1 * al1 + cs1;
        mrow0 = mn0; mrow1 = mn1;
#pragma unroll
        for (int nt = 0; nt < 12; nt++) {
            o[nt][0] *= al0; o[nt][1] *= al0; o[nt][2] *= al1; o[nt][3] *= al1;
        }
        __syncwarp();

#pragma unroll
        for (int kk = 0; kk < 64; kk += 16) {
            uint32_t a[4];
            ldmA4(a, &Ps[(w * 16 + (lane & 15)) * 72 + kk + (lane >> 4) * 8]);
#pragma unroll
            for (int nt = 0; nt < 12; nt += 2) {
                uint32_t bb[4];
                ldmB4t(bb, &Vs[(kk + (lane & 15)) * 104 + nt * 8 + (lane >> 4) * 8]);
                mma16816h(o[nt],     a, bb);
                mma16816h(o[nt + 1], a, bb + 2);
            }
        }
    }

    const float iv0 = 1.f / lrow0, iv1 = 1.f / lrow1;
#pragma unroll
    for (int nt = 0; nt < 12; nt++) {
        int d = h * HS + nt * 8 + tig * 2;
        {
            size_t orow = (size_t)(b * TT + qb0 + w * 16 + gid) * E2;
            float v0 = o[nt][0] * iv0, v1 = o[nt][1] * iv0;
            fp16 h0, l0, h1, l1; split2h(v0, h0, l0); split2h(v1, h1, l1);
            *(uint32_t*)&att2[orow + d]      = pack2h(h0, h1);
            *(uint32_t*)&att2[orow + EE + d] = pack2h(l0, l1);
        }
        {
            size_t orow = (size_t)(b * TT + qb0 + w * 16 + gid + 8) * E2;
            float v0 = o[nt][2] * iv1, v1 = o[nt][3] * iv1;
            fp16 h0, l0, h1, l1; split2h(v0, h0, l0); split2h(v1, h1, l1);
            *(uint32_t*)&att2[orow + d]      = pack2h(h0, h1);
            *(uint32_t*)&att2[orow + EE + d] = pack2h(l0, l1);
        }
    }
}

// ---------------- loss (single pass, online logsumexp, float4 reads) ---------------
__global__ void loss_zero_kernel(float* loss) { *loss = 0.f; }

__global__ void loss_kernel(const float* __restrict__ logits,
                            const int* __restrict__ targets,
                            float* __restrict__ loss)
{
    const int row = blockIdx.x;
    const int tid = threadIdx.x;   // 256
    const float* lr = logits + (size_t)row * VV;

    float m = -1e30f, s = 0.f;
    for (int j4 = tid; j4 < VV / 4; j4 += 256) {
        float4 f = *(const float4*)&lr[j4 * 4];
        float vals[4] = {f.x, f.y, f.z, f.w};
#pragma unroll
        for (int q = 0; q < 4; q++) {
            float v = vals[q];
            if (v > m) { s = s * __expf(m - v) + 1.f; m = v; }
            else       { s += __expf(v - m); }
        }
    }
    __shared__ float rm[256], rs[256];
    rm[tid] = m; rs[tid] = s; __syncthreads();
    for (int o = 128; o > 0; o >>= 1) {
        if (tid < o) {
            float m2 = rm[tid + o], s2 = rs[tid + o];
            float mm = fmaxf(rm[tid], m2);
            rs[tid] = rs[tid] * __expf(rm[tid] - mm) + s2 * __expf(m2 - mm);
            rm[tid] = mm;
        }
        __syncthreads();
    }
    if (tid == 0) {
        float lp = lr[targets[row]] - rm[0] - logf(rs[0]);
        atomicAdd(loss, -lp * (1.f / (float)MM));
    }
}

// ---------------- launch ----------------
extern "C" void kernel_launch(void* const* d_in, const int* in_sizes, int n_in,
                              void* d_out, int out_size)
{
    const int*   idx     = (const int*)  d_in[0];
    const int*   targets = (const int*)  d_in[1];
    const float* tok     = (const float*)d_in[2];
    const float* pos     = (const float*)d_in[3];
    const float* Wq      = (const float*)d_in[4];
    const float* Wk      = (const float*)d_in[5];
    const float* Wv      = (const float*)d_in[6];
    const float* Wo      = (const float*)d_in[7];
    const float* bo      = (const float*)d_in[8];
    const float* ln1_g   = (const float*)d_in[9];
    const float* ln1_b   = (const float*)d_in[10];
    const float* ln2_g   = (const float*)d_in[11];
    const float* ln2_b   = (const float*)d_in[12];
    const float* W1      = (const float*)d_in[13];
    const float* b1      = (const float*)d_in[14];
    const float* W2      = (const float*)d_in[15];
    const float* b2      = (const float*)d_in[16];
    const float* lnf_g   = (const float*)d_in[17];
    const float* lnf_b   = (const float*)d_in[18];

    float *x, *lg_scratch;
    fp16 *xn2, *qkv, *att2, *h42, *wqkv2, *wo2, *w12, *w22, *tok2;
    cudaGetSymbolAddress((void**)&x,    g_x);
    cudaGetSymbolAddress((void**)&xn2,  g_xn2);
    cudaGetSymbolAddress((void**)&qkv,  g_qkv);
    cudaGetSymbolAddress((void**)&att2, g_att2);
    cudaGetSymbolAddress((void**)&h42,  g_h42);
    cudaGetSymbolAddress((void**)&wqkv2,g_wqkv2);
    cudaGetSymbolAddress((void**)&wo2,  g_wo2);
    cudaGetSymbolAddress((void**)&w12,  g_w12);
    cudaGetSymbolAddress((void**)&w22,  g_w22);
    cudaGetSymbolAddress((void**)&tok2, g_tok2);
    cudaGetSymbolAddress((void**)&lg_scratch, g_logits_scratch);

    const int GEMM_SMEM = 73728;
    const int ATTN_SMEM = 72192;
    cudaFuncSetAttribute(mma_gemm<2,false>, cudaFuncAttributeMaxDynamicSharedMemorySize, GEMM_SMEM);
    cudaFuncSetAttribute(mma_gemm<2,true >, cudaFuncAttributeMaxDynamicSharedMemorySize, GEMM_SMEM);
    cudaFuncSetAttribute(mma_gemm<0,false>, cudaFuncAttributeMaxDynamicSharedMemorySize, GEMM_SMEM);
    cudaFuncSetAttribute(attn_mma_kernel, cudaFuncAttributeMaxDynamicSharedMemorySize, ATTN_SMEM);

    const bool out_holds_logits = ((long long)out_size >= (long long)MM * VV);
    float* logits = out_holds_logits ? (float*)d_out : lg_scratch;
    float* loss_ptr = out_holds_logits ? ((float*)d_out + (size_t)MM * VV)
                                       : (float*)d_out;
    const bool do_loss = (!out_holds_logits || (long long)out_size > (long long)MM * VV);

    convert_all_kernel<<<dim3(2304, 48), 256>>>(Wq, Wk, Wv, Wo, W1, W2);
    convert_tok_kernel<<<dim3(EE / 32, VV / 32), dim3(32, 32)>>>(tok, tok2);
    {
        size_t n = (size_t)MM * EE;
        embed_kernel<<<(unsigned)((n + 255) / 256), 256>>>(idx, tok, pos, x);
    }
    if (do_loss) loss_zero_kernel<<<1, 1>>>(loss_ptr);

    const int MAXCTA = 304;   // 2 CTAs/SM x 152 SMs
    auto pgrid = [&](int N) { int t = (MM / 128) * (N / 128); return t < MAXCTA ? t : MAXCTA; };
    const int gQKV = pgrid(E3);
    const int gEc  = pgrid(EE);
    const int gFc  = pgrid(FF);
    const int gVc  = pgrid(VV);
    const int LN_GRID = MM / 8;

    for (int l = 0; l < LL; l++) {
        // ln1 -> 1-term; qkv = xn1 @ Wqkv (1-term, K=768)
        ln_split_kernel<<<LN_GRID, 256>>>(x, ln1_g + (size_t)l * EE, ln1_b + (size_t)l * EE, xn2);
        mma_gemm<2, false><<<gQKV, 256, GEMM_SMEM>>>(xn2, wqkv2 + (size_t)l * EE * E3,
                                                     nullptr, nullptr, qkv, MM, E3, EE, EE);
        attn_mma_kernel<<<dim3(TT / 128, HH, BB), 256, ATTN_SMEM>>>(qkv, att2);
        // x = x + att @ Wo + bo  (2-term A)
        mma_gemm<0, false><<<gEc, 256, GEMM_SMEM>>>(att2, wo2 + (size_t)l * E2 * EE,
                                                    bo + (size_t)l * EE, x, x, MM, EE, E2, E2);
        // ln2 -> 1-term; h4 = round(gelu(xn @ W1 + b1))  (1-term, K=768)
        ln_split_kernel<<<LN_GRID, 256>>>(x, ln2_g + (size_t)l * EE, ln2_b + (size_t)l * EE, xn2);
        mma_gemm<2, true><<<gFc, 256, GEMM_SMEM>>>(xn2, w12 + (size_t)l * EE * FF,
                                                   b1 + (size_t)l * FF, nullptr, h42, MM, FF, EE, EE);
        // x = x + h4 @ W2 + b2  (1-term A, K=3072)
        mma_gemm<0, false><<<gEc, 256, GEMM_SMEM>>>(h42, w22 + (size_t)l * FF * EE,
                                                    b2 + (size_t)l * EE, x, x, MM, EE, FF, FF);
    }

    // lnf -> 1-term; lm-head 1-term A/B
    ln_split_kernel<<<LN_GRID, 256>>>(x, lnf_g, lnf_b, xn2);
    mma_gemm<0, false><<<gVc, 256, GEMM_SMEM>>>(xn2, tok2, nullptr, nullptr,
                                                logits, MM, VV, EE, EE);

    if (do_loss) loss_kernel<<<MM, 256>>>(logits, targets, loss_ptr);
}